// round 1
// baseline (speedup 1.0000x reference)
#include <cuda_runtime.h>
#include <math.h>

// ---------------- problem constants ----------------
#define BT     40          // B*T
#define NTOK   199         // 1 cls + 196 patches + 2 face
#define DIMc   768
#define MLPD   3072
#define NPATCH 196
#define HEADSc 12
#define DHc    64
#define DEPTHc 12
#define MROWS  (BT*NTOK)    // 7960
#define MPE    (BT*NPATCH)  // 7840

// ---------------- scratch (device globals; no runtime alloc) ----------------
__device__ float g_x[MROWS*DIMc];
__device__ float g_h[MROWS*DIMc];
__device__ float g_qkv[MROWS*3*DIMc];
__device__ float g_o[MROWS*DIMc];
__device__ float g_mlp[MROWS*MLPD];
__device__ float g_im2col[MPE*DIMc];
__device__ float g_wt[DIMc*DIMc];
__device__ float g_pe[MPE*DIMc];

// ---------------- conv_w transpose: (out=768, in=768) -> (in, out) ----------------
__global__ void transpose_w_kernel(const float* __restrict__ w) {
    int idx = blockIdx.x * 256 + threadIdx.x;
    if (idx >= DIMc*DIMc) return;
    int n = idx / DIMc, k = idx % DIMc;       // w[n][k]
    g_wt[k*DIMc + n] = w[idx];
}

// ---------------- im2col: (bt, patch) x (c,kh,kw) ----------------
__global__ void im2col_kernel(const float* __restrict__ img) {
    int idx = blockIdx.x * 256 + threadIdx.x;
    if (idx >= MPE*DIMc) return;
    int k = idx % DIMc, r = idx / DIMc;
    int bt = r / NPATCH, p = r % NPATCH;
    int c = k >> 8, rem = k & 255, kh = rem >> 4, kw = rem & 15;
    int ph = p / 14, pw = p % 14;
    size_t src = ((size_t)bt*3 + c)*224*224 + (size_t)(ph*16+kh)*224 + (pw*16+kw);
    g_im2col[idx] = img[src];
}

// ---------------- SGEMM: C[M,N] = A[M,K] @ B[K,N] (+epilogue) ----------------
// EPI: 0 = C=acc(+bias); 1 = C=gelu(acc+bias); 2 = C=C+acc+bias (residual)
// Requirements: N % 128 == 0, K % 16 == 0. M guarded.
template<int EPI>
__global__ __launch_bounds__(256)
void sgemm_kernel(const float* __restrict__ A, const float* __restrict__ B,
                  float* __restrict__ C, int M, int N, int K,
                  const float* __restrict__ bias)
{
    __shared__ float As[16][128];
    __shared__ float Bs[16][128];
    const int tid = threadIdx.x;
    const int tx  = tid & 15;       // 0..15 -> N
    const int ty  = tid >> 4;       // 0..15 -> M
    const int bm  = blockIdx.y * 128;
    const int bn  = blockIdx.x * 128;

    float acc[8][8];
    #pragma unroll
    for (int i = 0; i < 8; i++)
        #pragma unroll
        for (int j = 0; j < 8; j++) acc[i][j] = 0.f;

    for (int k0 = 0; k0 < K; k0 += 16) {
        // load A tile 128x16 (transpose into As[k][m])
        #pragma unroll
        for (int s = 0; s < 2; s++) {
            int idx = tid + s*256;             // 0..511 float4 slots
            int row = idx >> 2;                // 0..127
            int kq  = (idx & 3) << 2;          // 0,4,8,12
            float4 a = make_float4(0.f,0.f,0.f,0.f);
            if (bm + row < M)
                a = *(const float4*)&A[(size_t)(bm+row)*K + k0 + kq];
            As[kq+0][row] = a.x; As[kq+1][row] = a.y;
            As[kq+2][row] = a.z; As[kq+3][row] = a.w;
        }
        // load B tile 16x128
        #pragma unroll
        for (int s = 0; s < 2; s++) {
            int idx = tid + s*256;
            int row = idx >> 5;                // 0..15
            int nq  = (idx & 31) << 2;         // 0..124
            *(float4*)&Bs[row][nq] = *(const float4*)&B[(size_t)(k0+row)*N + bn + nq];
        }
        __syncthreads();

        #pragma unroll
        for (int k = 0; k < 16; k++) {
            float a[8], b[8];
            *(float4*)&a[0] = *(float4*)&As[k][ty*8];
            *(float4*)&a[4] = *(float4*)&As[k][ty*8+4];
            *(float4*)&b[0] = *(float4*)&Bs[k][tx*8];
            *(float4*)&b[4] = *(float4*)&Bs[k][tx*8+4];
            #pragma unroll
            for (int i = 0; i < 8; i++)
                #pragma unroll
                for (int j = 0; j < 8; j++)
                    acc[i][j] = fmaf(a[i], b[j], acc[i][j]);
        }
        __syncthreads();
    }

    // epilogue (vectorized by 4 along N)
    #pragma unroll
    for (int i = 0; i < 8; i++) {
        int row = bm + ty*8 + i;
        if (row >= M) continue;
        #pragma unroll
        for (int jq = 0; jq < 2; jq++) {
            int col = bn + tx*8 + jq*4;
            float4 v;
            v.x = acc[i][jq*4+0]; v.y = acc[i][jq*4+1];
            v.z = acc[i][jq*4+2]; v.w = acc[i][jq*4+3];
            if (bias) {
                float4 bb = *(const float4*)&bias[col];
                v.x += bb.x; v.y += bb.y; v.z += bb.z; v.w += bb.w;
            }
            if (EPI == 1) {
                v.x = 0.5f*v.x*(1.f+erff(v.x*0.70710678118654752f));
                v.y = 0.5f*v.y*(1.f+erff(v.y*0.70710678118654752f));
                v.z = 0.5f*v.z*(1.f+erff(v.z*0.70710678118654752f));
                v.w = 0.5f*v.w*(1.f+erff(v.w*0.70710678118654752f));
            }
            float* cp = &C[(size_t)row*N + col];
            if (EPI == 2) {
                float4 c0 = *(float4*)cp;
                v.x += c0.x; v.y += c0.y; v.z += c0.z; v.w += c0.w;
            }
            *(float4*)cp = v;
        }
    }
}

// ---------------- x assembly: cls/pos/patch/face/time ----------------
__global__ void assemble_kernel(const float* __restrict__ face,
                                const float* __restrict__ conv_b,
                                const float* __restrict__ pos,
                                const float* __restrict__ time_emb,
                                const float* __restrict__ cls)
{
    int idx = blockIdx.x * 256 + threadIdx.x;
    if (idx >= MROWS*DIMc) return;
    int d = idx % DIMc;
    int r = idx / DIMc;
    int tok = r % NTOK, bt = r / NTOK;
    int t = bt % 20;
    float v;
    if (tok == 0)
        v = cls[d] + pos[d];
    else if (tok <= NPATCH)
        v = g_pe[(size_t)(bt*NPATCH + tok - 1)*DIMc + d] + conv_b[d] + pos[tok*DIMc + d];
    else
        v = face[(size_t)(bt*2 + (tok - NPATCH - 1))*DIMc + d];
    g_x[idx] = v + time_emb[t*DIMc + d];
}

// ---------------- layernorm: row-wise over 768 ----------------
__global__ __launch_bounds__(256)
void ln_kernel(const float* __restrict__ x, float* __restrict__ y,
               const float* __restrict__ s, const float* __restrict__ b)
{
    int row = blockIdx.x;
    const float* xr = x + (size_t)row*DIMc;
    int t = threadIdx.x;
    float v0 = xr[t], v1 = xr[t+256], v2 = xr[t+512];
    float sum = v0+v1+v2;
    float sq  = v0*v0 + v1*v1 + v2*v2;
    #pragma unroll
    for (int off = 16; off > 0; off >>= 1) {
        sum += __shfl_down_sync(0xffffffffu, sum, off);
        sq  += __shfl_down_sync(0xffffffffu, sq,  off);
    }
    __shared__ float ssum[8], ssq[8];
    __shared__ float s_mean, s_rstd;
    if ((t & 31) == 0) { ssum[t>>5] = sum; ssq[t>>5] = sq; }
    __syncthreads();
    if (t == 0) {
        float S = 0.f, Q = 0.f;
        #pragma unroll
        for (int i = 0; i < 8; i++) { S += ssum[i]; Q += ssq[i]; }
        float m = S * (1.f/768.f);
        float var = Q * (1.f/768.f) - m*m;
        s_mean = m;
        s_rstd = rsqrtf(var + 1e-5f);
    }
    __syncthreads();
    float m = s_mean, rs = s_rstd;
    float* yr = y + (size_t)row*DIMc;
    yr[t]     = (v0 - m)*rs*s[t]     + b[t];
    yr[t+256] = (v1 - m)*rs*s[t+256] + b[t+256];
    yr[t+512] = (v2 - m)*rs*s[t+512] + b[t+512];
}

// ---------------- attention: one block per (bt, head), flash-style ----------------
__global__ __launch_bounds__(256)
void attn_kernel(const float* __restrict__ qkv, float* __restrict__ o)
{
    extern __shared__ float sm[];
    float* ks = sm;                 // [NTOK][64]
    float* vs = sm + NTOK*64;       // [NTOK][64]
    int bh = blockIdx.x;
    int bt = bh / HEADSc, h = bh % HEADSc;
    const float* base = qkv + (size_t)bt*NTOK*3*DIMc + h*DHc;

    for (int idx = threadIdx.x; idx < NTOK*16; idx += 256) {
        int j = idx >> 4, dd = (idx & 15) << 2;
        *(float4*)&ks[j*64+dd] = *(const float4*)&base[(size_t)j*2304 + 768  + dd];
        *(float4*)&vs[j*64+dd] = *(const float4*)&base[(size_t)j*2304 + 1536 + dd];
    }
    __syncthreads();

    int i = threadIdx.x;
    if (i >= NTOK) return;

    float q[64], oacc[64];
    #pragma unroll
    for (int dd = 0; dd < 16; dd++)
        *(float4*)&q[dd*4] = *(const float4*)&base[(size_t)i*2304 + dd*4];
    #pragma unroll
    for (int d = 0; d < 64; d++) oacc[d] = 0.f;

    float m = -1e30f, l = 0.f;
    for (int j = 0; j < NTOK; j++) {
        float dot = 0.f;
        const float* kj = &ks[j*64];
        #pragma unroll
        for (int d = 0; d < 64; d++) dot = fmaf(q[d], kj[d], dot);
        dot *= 0.125f;                          // DH^-0.5
        float mn   = fmaxf(m, dot);
        float corr = __expf(m - mn);
        float p    = __expf(dot - mn);
        l = l*corr + p;
        const float* vj = &vs[j*64];
        #pragma unroll
        for (int d = 0; d < 64; d++) oacc[d] = fmaf(oacc[d], corr, p * vj[d]);
        m = mn;
    }
    float inv = 1.f / l;
    float* orow = o + (size_t)(bt*NTOK + i)*DIMc + h*DHc;
    #pragma unroll
    for (int d = 0; d < 64; d++) orow[d] = oacc[d] * inv;
}

// ---------------- output scatter ----------------
__global__ void scatter_kernel(float* __restrict__ out)
{
    int idx = blockIdx.x * 256 + threadIdx.x;
    if (idx >= MROWS*DIMc) return;
    int d = idx % DIMc;
    int r = idx / DIMc;
    int tok = r % NTOK, bt = r / NTOK;
    float v = g_x[idx];
    int dst;
    if (tok == 0)        dst = bt*DIMc + d;
    else if (tok == 197) dst = BT*DIMc   + bt*DIMc + d;
    else if (tok == 198) dst = 2*BT*DIMc + bt*DIMc + d;
    else                 dst = 3*BT*DIMc + (bt*NPATCH + tok - 1)*DIMc + d;
    out[dst] = v;
}

// ---------------- launch ----------------
static inline int ceil_div(int a, int b) { return (a + b - 1) / b; }

extern "C" void kernel_launch(void* const* d_in, const int* in_sizes, int n_in,
                              void* d_out, int out_size)
{
    const float* img      = (const float*)d_in[0];
    const float* face     = (const float*)d_in[1];
    const float* conv_w   = (const float*)d_in[2];
    const float* conv_b   = (const float*)d_in[3];
    const float* pos_emb  = (const float*)d_in[4];
    const float* time_emb = (const float*)d_in[5];
    const float* cls_tok  = (const float*)d_in[6];
    const float* ln1_s    = (const float*)d_in[7];
    const float* ln1_b    = (const float*)d_in[8];
    const float* qkv_w    = (const float*)d_in[9];
    const float* out_w    = (const float*)d_in[10];
    const float* out_b    = (const float*)d_in[11];
    const float* ln2_s    = (const float*)d_in[12];
    const float* ln2_b    = (const float*)d_in[13];
    const float* ff_w1    = (const float*)d_in[14];
    const float* ff_b1    = (const float*)d_in[15];
    const float* ff_w2    = (const float*)d_in[16];
    const float* ff_b2    = (const float*)d_in[17];
    float* out = (float*)d_out;

    float *px, *ph, *pqkv, *po, *pmlp, *pim, *pwt, *ppe;
    cudaGetSymbolAddress((void**)&px,   g_x);
    cudaGetSymbolAddress((void**)&ph,   g_h);
    cudaGetSymbolAddress((void**)&pqkv, g_qkv);
    cudaGetSymbolAddress((void**)&po,   g_o);
    cudaGetSymbolAddress((void**)&pmlp, g_mlp);
    cudaGetSymbolAddress((void**)&pim,  g_im2col);
    cudaGetSymbolAddress((void**)&pwt,  g_wt);
    cudaGetSymbolAddress((void**)&ppe,  g_pe);

    const int ATTN_SMEM = 2*NTOK*64*(int)sizeof(float);  // 101888 B
    cudaFuncSetAttribute(attn_kernel, cudaFuncAttributeMaxDynamicSharedMemorySize, ATTN_SMEM);

    // --- patch embed ---
    transpose_w_kernel<<<ceil_div(DIMc*DIMc,256), 256>>>(conv_w);
    im2col_kernel<<<ceil_div(MPE*DIMc,256), 256>>>(img);
    {
        dim3 grid(DIMc/128, ceil_div(MPE,128));
        sgemm_kernel<0><<<grid, 256>>>(pim, pwt, ppe, MPE, DIMc, DIMc, nullptr);
    }
    assemble_kernel<<<ceil_div(MROWS*DIMc,256), 256>>>(face, conv_b, pos_emb, time_emb, cls_tok);

    // --- transformer layers ---
    for (int L = 0; L < DEPTHc; L++) {
        const float* qw  = qkv_w + (size_t)L*DIMc*3*DIMc;
        const float* ow  = out_w + (size_t)L*DIMc*DIMc;
        const float* ob  = out_b + (size_t)L*DIMc;
        const float* w1  = ff_w1 + (size_t)L*DIMc*MLPD;
        const float* b1  = ff_b1 + (size_t)L*MLPD;
        const float* w2  = ff_w2 + (size_t)L*MLPD*DIMc;
        const float* b2  = ff_b2 + (size_t)L*DIMc;

        ln_kernel<<<MROWS, 256>>>(px, ph, ln1_s + L*DIMc, ln1_b + L*DIMc);
        {
            dim3 grid((3*DIMc)/128, ceil_div(MROWS,128));
            sgemm_kernel<0><<<grid, 256>>>(ph, qw, pqkv, MROWS, 3*DIMc, DIMc, nullptr);
        }
        attn_kernel<<<BT*HEADSc, 256, ATTN_SMEM>>>(pqkv, po);
        {
            dim3 grid(DIMc/128, ceil_div(MROWS,128));
            sgemm_kernel<2><<<grid, 256>>>(po, ow, px, MROWS, DIMc, DIMc, ob);
        }
        ln_kernel<<<MROWS, 256>>>(px, ph, ln2_s + L*DIMc, ln2_b + L*DIMc);
        {
            dim3 grid(MLPD/128, ceil_div(MROWS,128));
            sgemm_kernel<1><<<grid, 256>>>(ph, w1, pmlp, MROWS, MLPD, DIMc, b1);
        }
        {
            dim3 grid(DIMc/128, ceil_div(MROWS,128));
            sgemm_kernel<2><<<grid, 256>>>(pmlp, w2, px, MROWS, DIMc, MLPD, b2);
        }
    }

    scatter_kernel<<<ceil_div(MROWS*DIMc,256), 256>>>(out);
}

// round 2
// speedup vs baseline: 2.4709x; 2.4709x over previous
#include <cuda_runtime.h>
#include <math.h>
#include <stdint.h>

// ---------------- problem constants ----------------
#define BT     40          // B*T
#define NTOK   199         // 1 cls + 196 patches + 2 face
#define DIMc   768
#define MLPD   3072
#define NPATCH 196
#define HEADSc 12
#define DHc    64
#define DEPTHc 12
#define MROWS  (BT*NTOK)    // 7960
#define MPE    (BT*NPATCH)  // 7840

// ---------------- scratch (device globals; no runtime alloc) ----------------
__device__ float g_x[MROWS*DIMc];
__device__ float g_h[MROWS*DIMc];
__device__ float g_qkv[MROWS*3*DIMc];
__device__ float g_o[MROWS*DIMc];
__device__ float g_mlp[MROWS*MLPD];
__device__ float g_im2col[MPE*DIMc];
__device__ float g_wt[DIMc*DIMc];
__device__ float g_pe[MPE*DIMc];

// ---------------- helpers ----------------
__device__ __forceinline__ uint32_t f2tf32(float f) {
    uint32_t u;
    asm("cvt.rna.tf32.f32 %0, %1;" : "=r"(u) : "f"(f));
    return u;
}

__device__ __forceinline__ void mma_tf32(float (&c)[4], const uint32_t (&a)[4],
                                         const uint32_t (&b)[2]) {
    asm volatile(
        "mma.sync.aligned.m16n8k8.row.col.f32.tf32.tf32.f32 "
        "{%0,%1,%2,%3}, {%4,%5,%6,%7}, {%8,%9}, {%0,%1,%2,%3};"
        : "+f"(c[0]), "+f"(c[1]), "+f"(c[2]), "+f"(c[3])
        : "r"(a[0]), "r"(a[1]), "r"(a[2]), "r"(a[3]),
          "r"(b[0]), "r"(b[1]));
}

// ---------------- conv_w transpose: (out=768, in=768) -> (in, out) ----------------
__global__ void transpose_w_kernel(const float* __restrict__ w) {
    int idx = blockIdx.x * 256 + threadIdx.x;
    if (idx >= DIMc*DIMc) return;
    int n = idx / DIMc, k = idx % DIMc;       // w[n][k]
    g_wt[k*DIMc + n] = w[idx];
}

// ---------------- im2col: (bt, patch) x (c,kh,kw) ----------------
__global__ void im2col_kernel(const float* __restrict__ img) {
    int idx = blockIdx.x * 256 + threadIdx.x;
    if (idx >= MPE*DIMc) return;
    int k = idx % DIMc, r = idx / DIMc;
    int bt = r / NPATCH, p = r % NPATCH;
    int c = k >> 8, rem = k & 255, kh = rem >> 4, kw = rem & 15;
    int ph = p / 14, pw = p % 14;
    size_t src = ((size_t)bt*3 + c)*224*224 + (size_t)(ph*16+kh)*224 + (pw*16+kw);
    g_im2col[idx] = img[src];
}

// ---------------- TF32 tensor-core GEMM ----------------
// C[M,N] = A[M,K] @ B[K,N] (+epilogue)
// EPI: 0 = C=acc(+bias); 1 = C=gelu(acc+bias); 2 = C=C+acc+bias (residual)
// Requirements: N % 128 == 0, K % 32 == 0. M guarded.
// Block tile 128x128, 8 warps, each warp 64x32 (warp grid 2x4), K-tile 32.
#define SA 36    // As stride in words ([m][k] layout) -> conflict-free frag loads & STS.128
#define SB 136   // Bs stride in words ([k][n] layout) -> conflict-free frag loads & STS.128

template<int EPI>
__global__ __launch_bounds__(256)
void tgemm_kernel(const float* __restrict__ A, const float* __restrict__ B,
                  float* __restrict__ C, int M, int N, int K,
                  const float* __restrict__ bias)
{
    __shared__ uint32_t As[128*SA];   // 18432 B
    __shared__ uint32_t Bs[32*SB];    // 17408 B
    const int tid   = threadIdx.x;
    const int lane  = tid & 31;
    const int warp  = tid >> 5;
    const int wm    = warp >> 2;          // 0..1
    const int wn    = warp & 3;           // 0..3
    const int group = lane >> 2;          // 0..7
    const int tig   = lane & 3;           // 0..3
    const int bm    = blockIdx.y * 128;
    const int bn    = blockIdx.x * 128;

    float acc[4][4][4];
    #pragma unroll
    for (int mf = 0; mf < 4; mf++)
        #pragma unroll
        for (int nf = 0; nf < 4; nf++)
            #pragma unroll
            for (int i = 0; i < 4; i++) acc[mf][nf][i] = 0.f;

    for (int k0 = 0; k0 < K; k0 += 32) {
        // ---- load A tile (128 x 32), keep [m][k] layout ----
        #pragma unroll
        for (int s = 0; s < 4; s++) {
            int slot = tid + s*256;          // 0..1023 float4 slots
            int row  = slot >> 3;            // 0..127
            int kq   = (slot & 7) << 2;      // 0..28
            float4 v = make_float4(0.f,0.f,0.f,0.f);
            if (bm + row < M)
                v = *(const float4*)&A[(size_t)(bm+row)*K + k0 + kq];
            uint4 u;
            u.x = f2tf32(v.x); u.y = f2tf32(v.y);
            u.z = f2tf32(v.z); u.w = f2tf32(v.w);
            *(uint4*)&As[row*SA + kq] = u;
        }
        // ---- load B tile (32 x 128), [k][n] layout ----
        #pragma unroll
        for (int s = 0; s < 4; s++) {
            int slot = tid + s*256;
            int krow = slot >> 5;            // 0..31
            int nq   = (slot & 31) << 2;     // 0..124
            float4 v = *(const float4*)&B[(size_t)(k0+krow)*N + bn + nq];
            uint4 u;
            u.x = f2tf32(v.x); u.y = f2tf32(v.y);
            u.z = f2tf32(v.z); u.w = f2tf32(v.w);
            *(uint4*)&Bs[krow*SB + nq] = u;
        }
        __syncthreads();

        #pragma unroll
        for (int kk = 0; kk < 32; kk += 8) {
            uint32_t af[4][4], bf[4][2];
            #pragma unroll
            for (int mf = 0; mf < 4; mf++) {
                int mrow = wm*64 + mf*16 + group;
                af[mf][0] = As[mrow*SA     + kk + tig];
                af[mf][1] = As[(mrow+8)*SA + kk + tig];
                af[mf][2] = As[mrow*SA     + kk + tig + 4];
                af[mf][3] = As[(mrow+8)*SA + kk + tig + 4];
            }
            #pragma unroll
            for (int nf = 0; nf < 4; nf++) {
                int ncol = wn*32 + nf*8 + group;
                bf[nf][0] = Bs[(kk+tig)*SB   + ncol];
                bf[nf][1] = Bs[(kk+tig+4)*SB + ncol];
            }
            #pragma unroll
            for (int mf = 0; mf < 4; mf++)
                #pragma unroll
                for (int nf = 0; nf < 4; nf++)
                    mma_tf32(acc[mf][nf], af[mf], bf[nf]);
        }
        __syncthreads();
    }

    // ---- epilogue ----
    #pragma unroll
    for (int mf = 0; mf < 4; mf++) {
        #pragma unroll
        for (int nf = 0; nf < 4; nf++) {
            int col = bn + wn*32 + nf*8 + tig*2;
            float bx = 0.f, by = 0.f;
            if (bias) { bx = bias[col]; by = bias[col+1]; }
            #pragma unroll
            for (int half = 0; half < 2; half++) {
                int row = bm + wm*64 + mf*16 + group + half*8;
                if (row >= M) continue;
                float vx = acc[mf][nf][half*2+0] + bx;
                float vy = acc[mf][nf][half*2+1] + by;
                if (EPI == 1) {
                    vx = 0.5f*vx*(1.f+erff(vx*0.70710678118654752f));
                    vy = 0.5f*vy*(1.f+erff(vy*0.70710678118654752f));
                }
                float* cp = &C[(size_t)row*N + col];
                if (EPI == 2) {
                    float2 c0 = *(float2*)cp;
                    vx += c0.x; vy += c0.y;
                }
                float2 vo; vo.x = vx; vo.y = vy;
                *(float2*)cp = vo;
            }
        }
    }
}

// ---------------- x assembly: cls/pos/patch/face/time ----------------
__global__ void assemble_kernel(const float* __restrict__ face,
                                const float* __restrict__ conv_b,
                                const float* __restrict__ pos,
                                const float* __restrict__ time_emb,
                                const float* __restrict__ cls)
{
    int idx = blockIdx.x * 256 + threadIdx.x;
    if (idx >= MROWS*DIMc) return;
    int d = idx % DIMc;
    int r = idx / DIMc;
    int tok = r % NTOK, bt = r / NTOK;
    int t = bt % 20;
    float v;
    if (tok == 0)
        v = cls[d] + pos[d];
    else if (tok <= NPATCH)
        v = g_pe[(size_t)(bt*NPATCH + tok - 1)*DIMc + d] + conv_b[d] + pos[tok*DIMc + d];
    else
        v = face[(size_t)(bt*2 + (tok - NPATCH - 1))*DIMc + d];
    g_x[idx] = v + time_emb[t*DIMc + d];
}

// ---------------- layernorm: row-wise over 768 ----------------
__global__ __launch_bounds__(256)
void ln_kernel(const float* __restrict__ x, float* __restrict__ y,
               const float* __restrict__ s, const float* __restrict__ b)
{
    int row = blockIdx.x;
    const float* xr = x + (size_t)row*DIMc;
    int t = threadIdx.x;
    float v0 = xr[t], v1 = xr[t+256], v2 = xr[t+512];
    float sum = v0+v1+v2;
    float sq  = v0*v0 + v1*v1 + v2*v2;
    #pragma unroll
    for (int off = 16; off > 0; off >>= 1) {
        sum += __shfl_down_sync(0xffffffffu, sum, off);
        sq  += __shfl_down_sync(0xffffffffu, sq,  off);
    }
    __shared__ float ssum[8], ssq[8];
    __shared__ float s_mean, s_rstd;
    if ((t & 31) == 0) { ssum[t>>5] = sum; ssq[t>>5] = sq; }
    __syncthreads();
    if (t == 0) {
        float S = 0.f, Q = 0.f;
        #pragma unroll
        for (int i = 0; i < 8; i++) { S += ssum[i]; Q += ssq[i]; }
        float m = S * (1.f/768.f);
        float var = Q * (1.f/768.f) - m*m;
        s_mean = m;
        s_rstd = rsqrtf(var + 1e-5f);
    }
    __syncthreads();
    float m = s_mean, rs = s_rstd;
    float* yr = y + (size_t)row*DIMc;
    yr[t]     = (v0 - m)*rs*s[t]     + b[t];
    yr[t+256] = (v1 - m)*rs*s[t+256] + b[t+256];
    yr[t+512] = (v2 - m)*rs*s[t+512] + b[t+512];
}

// ---------------- attention: one block per (bt, head), flash-style ----------------
__global__ __launch_bounds__(256)
void attn_kernel(const float* __restrict__ qkv, float* __restrict__ o)
{
    extern __shared__ float sm[];
    float* ks = sm;                 // [NTOK][64]
    float* vs = sm + NTOK*64;       // [NTOK][64]
    int bh = blockIdx.x;
    int bt = bh / HEADSc, h = bh % HEADSc;
    const float* base = qkv + (size_t)bt*NTOK*3*DIMc + h*DHc;

    for (int idx = threadIdx.x; idx < NTOK*16; idx += 256) {
        int j = idx >> 4, dd = (idx & 15) << 2;
        *(float4*)&ks[j*64+dd] = *(const float4*)&base[(size_t)j*2304 + 768  + dd];
        *(float4*)&vs[j*64+dd] = *(const float4*)&base[(size_t)j*2304 + 1536 + dd];
    }
    __syncthreads();

    int i = threadIdx.x;
    if (i >= NTOK) return;

    float q[64], oacc[64];
    #pragma unroll
    for (int dd = 0; dd < 16; dd++)
        *(float4*)&q[dd*4] = *(const float4*)&base[(size_t)i*2304 + dd*4];
    #pragma unroll
    for (int d = 0; d < 64; d++) oacc[d] = 0.f;

    float m = -1e30f, l = 0.f;
    for (int j = 0; j < NTOK; j++) {
        float dot = 0.f;
        const float* kj = &ks[j*64];
        #pragma unroll
        for (int d = 0; d < 64; d++) dot = fmaf(q[d], kj[d], dot);
        dot *= 0.125f;                          // DH^-0.5
        float mn   = fmaxf(m, dot);
        float corr = __expf(m - mn);
        float p    = __expf(dot - mn);
        l = l*corr + p;
        const float* vj = &vs[j*64];
        #pragma unroll
        for (int d = 0; d < 64; d++) oacc[d] = fmaf(oacc[d], corr, p * vj[d]);
        m = mn;
    }
    float inv = 1.f / l;
    float* orow = o + (size_t)(bt*NTOK + i)*DIMc + h*DHc;
    #pragma unroll
    for (int d = 0; d < 64; d++) orow[d] = oacc[d] * inv;
}

// ---------------- output scatter ----------------
__global__ void scatter_kernel(float* __restrict__ out)
{
    int idx = blockIdx.x * 256 + threadIdx.x;
    if (idx >= MROWS*DIMc) return;
    int d = idx % DIMc;
    int r = idx / DIMc;
    int tok = r % NTOK, bt = r / NTOK;
    float v = g_x[idx];
    int dst;
    if (tok == 0)        dst = bt*DIMc + d;
    else if (tok == 197) dst = BT*DIMc   + bt*DIMc + d;
    else if (tok == 198) dst = 2*BT*DIMc + bt*DIMc + d;
    else                 dst = 3*BT*DIMc + (bt*NPATCH + tok - 1)*DIMc + d;
    out[dst] = v;
}

// ---------------- launch ----------------
static inline int ceil_div(int a, int b) { return (a + b - 1) / b; }

extern "C" void kernel_launch(void* const* d_in, const int* in_sizes, int n_in,
                              void* d_out, int out_size)
{
    const float* img      = (const float*)d_in[0];
    const float* face     = (const float*)d_in[1];
    const float* conv_w   = (const float*)d_in[2];
    const float* conv_b   = (const float*)d_in[3];
    const float* pos_emb  = (const float*)d_in[4];
    const float* time_emb = (const float*)d_in[5];
    const float* cls_tok  = (const float*)d_in[6];
    const float* ln1_s    = (const float*)d_in[7];
    const float* ln1_b    = (const float*)d_in[8];
    const float* qkv_w    = (const float*)d_in[9];
    const float* out_w    = (const float*)d_in[10];
    const float* out_b    = (const float*)d_in[11];
    const float* ln2_s    = (const float*)d_in[12];
    const float* ln2_b    = (const float*)d_in[13];
    const float* ff_w1    = (const float*)d_in[14];
    const float* ff_b1    = (const float*)d_in[15];
    const float* ff_w2    = (const float*)d_in[16];
    const float* ff_b2    = (const float*)d_in[17];
    float* out = (float*)d_out;

    float *px, *ph, *pqkv, *po, *pmlp, *pim, *pwt, *ppe;
    cudaGetSymbolAddress((void**)&px,   g_x);
    cudaGetSymbolAddress((void**)&ph,   g_h);
    cudaGetSymbolAddress((void**)&pqkv, g_qkv);
    cudaGetSymbolAddress((void**)&po,   g_o);
    cudaGetSymbolAddress((void**)&pmlp, g_mlp);
    cudaGetSymbolAddress((void**)&pim,  g_im2col);
    cudaGetSymbolAddress((void**)&pwt,  g_wt);
    cudaGetSymbolAddress((void**)&ppe,  g_pe);

    const int ATTN_SMEM = 2*NTOK*64*(int)sizeof(float);  // 101888 B
    cudaFuncSetAttribute(attn_kernel, cudaFuncAttributeMaxDynamicSharedMemorySize, ATTN_SMEM);

    // --- patch embed ---
    transpose_w_kernel<<<ceil_div(DIMc*DIMc,256), 256>>>(conv_w);
    im2col_kernel<<<ceil_div(MPE*DIMc,256), 256>>>(img);
    {
        dim3 grid(DIMc/128, ceil_div(MPE,128));
        tgemm_kernel<0><<<grid, 256>>>(pim, pwt, ppe, MPE, DIMc, DIMc, nullptr);
    }
    assemble_kernel<<<ceil_div(MROWS*DIMc,256), 256>>>(face, conv_b, pos_emb, time_emb, cls_tok);

    // --- transformer layers ---
    for (int L = 0; L < DEPTHc; L++) {
        const float* qw  = qkv_w + (size_t)L*DIMc*3*DIMc;
        const float* ow  = out_w + (size_t)L*DIMc*DIMc;
        const float* ob  = out_b + (size_t)L*DIMc;
        const float* w1  = ff_w1 + (size_t)L*DIMc*MLPD;
        const float* b1  = ff_b1 + (size_t)L*MLPD;
        const float* w2  = ff_w2 + (size_t)L*MLPD*DIMc;
        const float* b2  = ff_b2 + (size_t)L*DIMc;

        ln_kernel<<<MROWS, 256>>>(px, ph, ln1_s + L*DIMc, ln1_b + L*DIMc);
        {
            dim3 grid((3*DIMc)/128, ceil_div(MROWS,128));
            tgemm_kernel<0><<<grid, 256>>>(ph, qw, pqkv, MROWS, 3*DIMc, DIMc, nullptr);
        }
        attn_kernel<<<BT*HEADSc, 256, ATTN_SMEM>>>(pqkv, po);
        {
            dim3 grid(DIMc/128, ceil_div(MROWS,128));
            tgemm_kernel<2><<<grid, 256>>>(po, ow, px, MROWS, DIMc, DIMc, ob);
        }
        ln_kernel<<<MROWS, 256>>>(px, ph, ln2_s + L*DIMc, ln2_b + L*DIMc);
        {
            dim3 grid(MLPD/128, ceil_div(MROWS,128));
            tgemm_kernel<1><<<grid, 256>>>(ph, w1, pmlp, MROWS, MLPD, DIMc, b1);
        }
        {
            dim3 grid(DIMc/128, ceil_div(MROWS,128));
            tgemm_kernel<2><<<grid, 256>>>(pmlp, w2, px, MROWS, DIMc, MLPD, b2);
        }
    }

    scatter_kernel<<<ceil_div(MROWS*DIMc,256), 256>>>(out);
}